// round 15
// baseline (speedup 1.0000x reference)
#include <cuda_runtime.h>
#include <cuda_bf16.h>
#include <mma.h>
#include <math.h>
#include <stdint.h>

using namespace nvcuda;

#define B_TOTAL 65536
#define NPAIR 16
typedef unsigned long long ull;

// Scratch: conv2 outputs as bf16 hi/lo, [B][256] bf16 = [B][128] u32 each.
__device__ uint32_t g_hi32[B_TOTAL * 128];
__device__ uint32_t g_lo32[B_TOTAL * 128];

// ---- f32x2 helpers -------------------------------------------------------
__device__ __forceinline__ ull pack2(float a, float b) {
    ull r; asm("mov.b64 %0, {%1,%2};" : "=l"(r) : "f"(a), "f"(b)); return r;
}
__device__ __forceinline__ void unpk(ull v, float& a, float& b) {
    asm("mov.b64 {%0,%1}, %2;" : "=f"(a), "=f"(b) : "l"(v));
}
__device__ __forceinline__ void ffma2(ull& d, ull a, ull b) {
    asm("fma.rn.f32x2 %0, %1, %2, %0;" : "+l"(d) : "l"(a), "l"(b));
}

// ---- bf16 pack helpers: result = bf16(lo16) | bf16(hi16)<<16 ----
__device__ __forceinline__ uint32_t cvt2bf(float lo16, float hi16) {
    uint32_t r;
    asm("cvt.rn.satfinite.bf16x2.f32 %0, %1, %2;" : "=r"(r) : "f"(hi16), "f"(lo16));
    return r;
}
__device__ __forceinline__ float bflo_f(uint32_t r) { return __uint_as_float(r << 16); }
__device__ __forceinline__ float bfhi_f(uint32_t r) { return __uint_as_float(r & 0xffff0000u); }

// sp1 padded layout: [ci][row 0..11][col 0..11], idx = ci*170 + row*14 + col
#define SP1_CI 170
#define SP1_ROW 14
#define SP1_SZ 340

// ---- k_conv dynamic smem layout (byte offsets, base 16-aligned) ----
#define OFF_SX   0                    // ull sx[2][784]  = 12544
#define OFF_SP1  12544                // ull sp1[2][340] =  5440
#define OFF_AHI  17984                // bf16 A hi [128][72] = 18432
#define OFF_ALO  36416                // bf16 A lo [128][72] = 18432
#define OFF_BHI  54848                // bf16 B hi [64][24]  =  3072
#define OFF_BLO  57920                // bf16 B lo [64][24]  =  3072
#define CONV_SMEM 60992
#define ALDM 72
#define BLDM 24

__device__ __forceinline__ void stage_pair(ull* buf, const float* __restrict__ x,
                                           long b0, int tid, int nt) {
    const float4* A = (const float4*)(x + b0 * 784);
    const float4* C = (const float4*)(x + (b0 + 1) * 784);
    for (int i = tid; i < 196; i += nt) {
        float4 a4 = __ldg(&A[i]), c4 = __ldg(&C[i]);
        ulonglong2 v01, v23;
        v01.x = pack2(a4.x, c4.x); v01.y = pack2(a4.y, c4.y);
        v23.x = pack2(a4.z, c4.z); v23.y = pack2(a4.w, c4.w);
        *(ulonglong2*)&buf[4 * i]     = v01;
        *(ulonglong2*)&buf[4 * i + 2] = v23;
    }
}

// ---------------------------------------------------------------------------
// k_conv: warp-specialized, conv2 on wmma.
//   warps 0-2 (t<96):   conv1+pool (pair it), FFMA2, wd1 resident.
//   warp 3  (96..127):  stage pair it+1.
//   warps 4-7 (128..255): conv2 (pair it-1): im2col A-build (bf16 hi/lo,
//     k = 2*(ky*5+kx)+ci, pad cols zeroed) -> warp-local wmma (2 m x 4 k x 3
//     terms) -> D to own smem -> 2x2 pool + bias + relu -> bf16 hi/lo store.
// ---------------------------------------------------------------------------
__global__ void __launch_bounds__(256, 2) k_conv(const float* __restrict__ x,
                                                 const float* __restrict__ w1,
                                                 const float* __restrict__ b1,
                                                 const float* __restrict__ w2,
                                                 const float* __restrict__ b2) {
    extern __shared__ __align__(16) char dsm[];
    ull* sx  = (ull*)(dsm + OFF_SX);
    ull* sp1 = (ull*)(dsm + OFF_SP1);
    __nv_bfloat16* s_ahi = (__nv_bfloat16*)(dsm + OFF_AHI);
    __nv_bfloat16* s_alo = (__nv_bfloat16*)(dsm + OFF_ALO);
    __nv_bfloat16* s_bhi = (__nv_bfloat16*)(dsm + OFF_BHI);
    __nv_bfloat16* s_blo = (__nv_bfloat16*)(dsm + OFF_BLO);

    const int t = threadIdx.x;
    const int wid = t >> 5, lane = t & 31;
    const long pair0 = (long)blockIdx.x * NPAIR;

    // ---- ph1 persistent weights ----
    ull wreg[25];
    float bias1 = 0.f;
    int co1 = 0, py1 = 0, pxh1 = 0;
    if (t < 96) {
        co1 = t / 48;
        const int rem = t % 48;
        py1 = rem >> 2; pxh1 = rem & 3;
#pragma unroll
        for (int i = 0; i < 25; i++) {
            float w = __ldg(&w1[co1 * 25 + i]);
            wreg[i] = pack2(w, w);
        }
        bias1 = __ldg(&b1[co1]);
    }
    // ph2 per-lane bias (co = lane>>1)
    const float bias2 = __ldg(&b2[(lane >> 1) & 15]);

    // ---- init: zero B (rows 50..63 must stay zero), stage weights, sx[0] ----
    {
        uint32_t* b32 = (uint32_t*)(dsm + OFF_BHI);
        for (int i = t; i < (2 * 64 * BLDM) / 2; i += 256) b32[i] = 0;  // hi+lo
    }
    stage_pair(sx, x, pair0 * 2, t, 256);
    __syncthreads();
    // B[k][co]: k = 2*(ky*5+kx)+ci, value = w2[co*50 + ci*25 + ky*5+kx]
    for (int i = t; i < 800; i += 256) {
        const int co = i / 50, j = i % 50;
        const int ci = j / 25, r = j % 25;
        const int krow = 2 * r + ci;
        float w = __ldg(&w2[co * 50 + ci * 25 + r]);
        __nv_bfloat16 hb = __float2bfloat16(w);
        s_bhi[krow * BLDM + co] = hb;
        s_blo[krow * BLDM + co] = __float2bfloat16(w - __bfloat162float(hb));
    }
    __syncthreads();

    // ---- main loop ----
    for (int it = 0; it <= NPAIR; it++) {
        if (t < 96) {
            // ph1: conv1 + relu + pool, pair it
            if (it < NPAIR) {
                const ull* in = &sx[(it & 1) * 784 + (2 * py1) * 28 + 6 * pxh1];
                ull acc[2][6] = {{0,0,0,0,0,0},{0,0,0,0,0,0}};
#pragma unroll
                for (int iy = 0; iy < 6; iy++) {
                    ull row[10];
#pragma unroll
                    for (int c = 0; c < 10; c += 2) {
                        ulonglong2 v = *(const ulonglong2*)&in[iy * 28 + c];
                        row[c] = v.x; row[c + 1] = v.y;
                    }
#pragma unroll
                    for (int yy = 0; yy < 2; yy++) {
                        const int ky = iy - yy;
                        if (ky >= 0 && ky < 5) {
#pragma unroll
                            for (int cx = 0; cx < 6; cx++)
#pragma unroll
                                for (int kx = 0; kx < 5; kx++)
                                    ffma2(acc[yy][cx], row[cx + kx], wreg[ky * 5 + kx]);
                        }
                    }
                }
                ull* op = &sp1[(it & 1) * SP1_SZ + co1 * SP1_CI + py1 * SP1_ROW + pxh1 * 3];
#pragma unroll
                for (int q = 0; q < 3; q++) {
                    float a0,a1,e0,e1,c0,c1,d0,d1;
                    unpk(acc[0][2*q],   a0,a1); unpk(acc[0][2*q+1], e0,e1);
                    unpk(acc[1][2*q],   c0,c1); unpk(acc[1][2*q+1], d0,d1);
                    float vA = fmaxf(fmaxf(fmaxf(a0,e0), fmaxf(c0,d0)) + bias1, 0.f);
                    float vB = fmaxf(fmaxf(fmaxf(a1,e1), fmaxf(c1,d1)) + bias1, 0.f);
                    op[q] = pack2(vA, vB);
                }
            }
        } else if (t < 128) {
            // stager: pair it+1
            if (it + 1 < NPAIR)
                stage_pair(&sx[((it + 1) & 1) * 784], x, (pair0 + it + 1) * 2, t - 96, 32);
        } else if (it >= 1) {
            // ---- ph2: conv2 on wmma, pair p = it-1 ----
            const int p = it - 1;
            const int u = t - 128;                 // 0..127 = A row
            const int wrel = wid - 4;              // 0..3
            const int s = u >> 6;                  // sample within pair (warp-uniform)
            const int pos = u & 63;
            const int y0 = pos >> 3, x0 = pos & 7; // conv output coords (pre-pool)

            // A-build: row u, patch base (y0, x0); k pairs ci-interleaved.
            {
                const ull* spb = &sp1[(p & 1) * SP1_SZ + y0 * SP1_ROW + x0];
                uint32_t* arh = (uint32_t*)(s_ahi + u * ALDM);
                uint32_t* arl = (uint32_t*)(s_alo + u * ALDM);
#pragma unroll
                for (int ky = 0; ky < 5; ky++) {
#pragma unroll
                    for (int kx = 0; kx < 5; kx++) {
                        ull v0 = spb[ky * SP1_ROW + kx];
                        ull v1 = spb[SP1_CI + ky * SP1_ROW + kx];
                        float a0, b0f, a1, b1f;
                        unpk(v0, a0, b0f); unpk(v1, a1, b1f);
                        const float f0 = s ? b0f : a0;
                        const float f1 = s ? b1f : a1;
                        uint32_t hi = cvt2bf(f0, f1);
                        uint32_t lo = cvt2bf(f0 - bflo_f(hi), f1 - bfhi_f(hi));
                        const int kk = ky * 5 + kx;
                        arh[kk] = hi;
                        arl[kk] = lo;
                    }
                }
                // zero pad k = 50..63 (u32 slots 25..31): kills NaN garbage
#pragma unroll
                for (int z = 25; z < 32; z++) { arh[z] = 0; arl[z] = 0; }
            }
            __syncwarp();

            // wmma: 2 m-tiles x 4 k-tiles x 3 terms, warp-local rows
            wmma::fragment<wmma::matrix_a, 16, 16, 16, __nv_bfloat16, wmma::row_major> ah, al;
            wmma::fragment<wmma::matrix_b, 16, 16, 16, __nv_bfloat16, wmma::row_major> bh, bl;
            wmma::fragment<wmma::accumulator, 16, 16, 16, float> acc[2];
#pragma unroll
            for (int mt = 0; mt < 2; mt++) wmma::fill_fragment(acc[mt], 0.0f);
#pragma unroll
            for (int kt = 0; kt < 4; kt++) {
                wmma::load_matrix_sync(bh, s_bhi + kt * 16 * BLDM, BLDM);
                wmma::load_matrix_sync(bl, s_blo + kt * 16 * BLDM, BLDM);
#pragma unroll
                for (int mt = 0; mt < 2; mt++) {
                    const __nv_bfloat16* ab  = s_ahi + (wrel * 32 + mt * 16) * ALDM + kt * 16;
                    const __nv_bfloat16* abl = s_alo + (wrel * 32 + mt * 16) * ALDM + kt * 16;
                    wmma::load_matrix_sync(ah, ab, ALDM);
                    wmma::load_matrix_sync(al, abl, ALDM);
                    wmma::mma_sync(acc[mt], ah, bh, acc[mt]);
                    wmma::mma_sync(acc[mt], al, bh, acc[mt]);
                    wmma::mma_sync(acc[mt], ah, bl, acc[mt]);
                }
            }

            // D -> own smem region (overwrites own A rows; pad re-zeroed next iter)
            float* dws = (float*)(s_ahi + wrel * 32 * ALDM);
#pragma unroll
            for (int mt = 0; mt < 2; mt++)
                wmma::store_matrix_sync(dws + mt * 16 * 16, acc[mt], 16, wmma::mem_row_major);
            __syncwarp();

            // 2x2 pool + bias + relu + bf16 hi/lo store
            {
                const int co = lane >> 1, pyl = lane & 1;
                float v[4];
#pragma unroll
                for (int px = 0; px < 4; px++) {
                    float m0 = dws[((2 * pyl)     * 8 + 2 * px)     * 16 + co];
                    float m1 = dws[((2 * pyl)     * 8 + 2 * px + 1) * 16 + co];
                    float m2 = dws[((2 * pyl + 1) * 8 + 2 * px)     * 16 + co];
                    float m3 = dws[((2 * pyl + 1) * 8 + 2 * px + 1) * 16 + co];
                    v[px] = fmaxf(fmaxf(fmaxf(m0, m1), fmaxf(m2, m3)) + bias2, 0.f);
                }
                uint32_t h01 = cvt2bf(v[0], v[1]);
                uint32_t h23 = cvt2bf(v[2], v[3]);
                uint32_t l01 = cvt2bf(v[0] - bflo_f(h01), v[1] - bfhi_f(h01));
                uint32_t l23 = cvt2bf(v[2] - bflo_f(h23), v[3] - bfhi_f(h23));
                const long b = (pair0 + p) * 2 + (wrel >> 1);
                const int py = 2 * (wrel & 1) + pyl;
                const int off = co * 8 + py * 2;
                *(uint2*)&g_hi32[b * 128 + off] = make_uint2(h01, h23);
                *(uint2*)&g_lo32[b * 128 + off] = make_uint2(l01, l23);
            }
        }
        __syncthreads();
    }
}

// ---------------------------------------------------------------------------
// k_fc: fc1 on wmma bf16 (3-term hi/lo) with smem-staged operands (R13, 69.9us).
// ---------------------------------------------------------------------------
#define WLDM 72
#define W_BYTES (256 * WLDM * 2)
#define A_CHUNK_BYTES (16 * WLDM * 2)
#define A_WARP_BYTES (2 * A_CHUNK_BYTES)
#define FC_SMEM (2 * W_BYTES + 8 * A_WARP_BYTES)

__global__ void __launch_bounds__(256) k_fc(const float* __restrict__ fc1w,
                                            const float* __restrict__ fc1b,
                                            const float* __restrict__ fc2w,
                                            const float* __restrict__ fc2b,
                                            const float* __restrict__ fc3w,
                                            const float* __restrict__ fc3b,
                                            const float* __restrict__ qp,
                                            float* __restrict__ out) {
    extern __shared__ __align__(16) char smem[];
    __nv_bfloat16* s_whi = (__nv_bfloat16*)smem;
    __nv_bfloat16* s_wlo = (__nv_bfloat16*)(smem + W_BYTES);
    char* s_awarp_base = smem + 2 * W_BYTES;

    const int tid = threadIdx.x, warp = tid >> 5, lane = tid & 31;

    __nv_bfloat16* s_ahi = (__nv_bfloat16*)(s_awarp_base + warp * A_WARP_BYTES);
    __nv_bfloat16* s_alo = s_ahi + 16 * WLDM;
    float* dw = (float*)s_ahi;

    for (int i = tid; i < 16384; i += 256) {
        const int n = i & 63, k = i >> 6;
        float w = __ldg(&fc1w[n * 256 + k]);
        __nv_bfloat16 hb = __float2bfloat16(w);
        s_whi[k * WLDM + n] = hb;
        s_wlo[k * WLDM + n] = __float2bfloat16(w - __bfloat162float(hb));
    }
    __syncthreads();

    const __nv_bfloat16* ghi = (const __nv_bfloat16*)g_hi32;
    const __nv_bfloat16* glo = (const __nv_bfloat16*)g_lo32;

    for (int c = 0; c < 2; c++) {
        const int tile = blockIdx.x * 16 + warp * 2 + c;
        const long sb = (long)tile * 16;

        wmma::fragment<wmma::matrix_a, 16, 16, 16, __nv_bfloat16, wmma::row_major> ah, al;
        wmma::fragment<wmma::matrix_b, 16, 16, 16, __nv_bfloat16, wmma::row_major> bh, bl;
        wmma::fragment<wmma::accumulator, 16, 16, 16, float> acc[4];
#pragma unroll
        for (int nt = 0; nt < 4; nt++) wmma::fill_fragment(acc[nt], 0.0f);

        for (int ck = 0; ck < 4; ck++) {
            __syncwarp();
#pragma unroll
            for (int ii = 0; ii < 4; ii++) {
                const int idx = lane + ii * 32;
                const int row = idx >> 3, seg = idx & 7;
                const long goff = (sb + row) * 256 + ck * 64 + seg * 8;
                *(uint4*)&s_ahi[row * WLDM + seg * 8] = __ldg((const uint4*)&ghi[goff]);
                *(uint4*)&s_alo[row * WLDM + seg * 8] = __ldg((const uint4*)&glo[goff]);
            }
            __syncwarp();
#pragma unroll
            for (int kcc = 0; kcc < 4; kcc++) {
                const int k0 = ck * 64 + kcc * 16;
                wmma::load_matrix_sync(ah, s_ahi + kcc * 16, WLDM);
                wmma::load_matrix_sync(al, s_alo + kcc * 16, WLDM);
#pragma unroll
                for (int nt = 0; nt < 4; nt++) {
                    wmma::load_matrix_sync(bh, s_whi + k0 * WLDM + nt * 16, WLDM);
                    wmma::load_matrix_sync(bl, s_wlo + k0 * WLDM + nt * 16, WLDM);
                    wmma::mma_sync(acc[nt], ah, bh, acc[nt]);
                    wmma::mma_sync(acc[nt], al, bh, acc[nt]);
                    wmma::mma_sync(acc[nt], ah, bl, acc[nt]);
                }
            }
        }
        __syncwarp();
#pragma unroll
        for (int nt = 0; nt < 4; nt++)
            wmma::store_matrix_sync(dw + nt * 16, acc[nt], 64, wmma::mem_row_major);
        __syncwarp();

        if (lane < 16) {
            const float* hrow = dw + lane * 64;
            float x0 = __ldg(&fc2b[0]), x1 = __ldg(&fc2b[1]);
#pragma unroll 8
            for (int o = 0; o < 64; o++) {
                const int o2 = (o + lane * 4) & 63;
                float v = fmaxf(hrow[o2] + __ldg(&fc1b[o2]), 0.f);
                x0 = fmaf(v, __ldg(&fc2w[o2]), x0);
                x1 = fmaf(v, __ldg(&fc2w[64 + o2]), x1);
            }

            float cq[8], sq[8];
#pragma unroll
            for (int i = 0; i < 8; i++) {
                float p = __ldg(&qp[i]);
                sincosf(p, &sq[i], &cq[i]);
            }
            const float PI = 3.14159265358979323846f;
            const float ang = (PI - x0) * (PI - x1);
            const float P = x0 + x1, M = x0 - x1;
            float sPp, cPp, sPm, cPm, sMp, cMp, sMm, cMm;
            sincosf(P + ang, &sPp, &cPp);
            sincosf(P - ang, &sPm, &cPm);
            sincosf(M + ang, &sMp, &cMp);
            sincosf(M - ang, &sMm, &cMm);
            float r00 =  0.5f * cPp, i00 = -0.5f * sPp;
            float r01 =  0.5f * cMm, i01 = -0.5f * sMm;
            float r10 =  0.5f * cMp, i10 =  0.5f * sMp;
            float r11 =  0.5f * cPm, i11 =  0.5f * sPm;

#define ROT0(ii) { float cc = cq[ii], s = sq[ii], a, bt;                     \
    a = r00; bt = r10; r00 = cc*a - s*bt; r10 = s*a + cc*bt;                 \
    a = i00; bt = i10; i00 = cc*a - s*bt; i10 = s*a + cc*bt;                 \
    a = r01; bt = r11; r01 = cc*a - s*bt; r11 = s*a + cc*bt;                 \
    a = i01; bt = i11; i01 = cc*a - s*bt; i11 = s*a + cc*bt; }
#define ROT1(ii) { float cc = cq[ii], s = sq[ii], a, bt;                     \
    a = r00; bt = r01; r00 = cc*a - s*bt; r01 = s*a + cc*bt;                 \
    a = i00; bt = i01; i00 = cc*a - s*bt; i01 = s*a + cc*bt;                 \
    a = r10; bt = r11; r10 = cc*a - s*bt; r11 = s*a + cc*bt;                 \
    a = i10; bt = i11; i10 = cc*a - s*bt; i11 = s*a + cc*bt; }
#define CN01 { float tt; tt = r10; r10 = r11; r11 = tt; tt = i10; i10 = i11; i11 = tt; }
#define CN10 { float tt; tt = r01; r01 = r11; r11 = tt; tt = i01; i01 = i11; i11 = tt; }

            ROT0(0); ROT1(1); CN01;
            ROT0(2); ROT1(3); CN10;
            ROT0(4); ROT1(5); CN01;
            ROT0(6); ROT1(7);

#undef ROT0
#undef ROT1
#undef CN01
#undef CN10

            const float q = (r00 * r00 + i00 * i00) - (r01 * r01 + i01 * i01)
                          - (r10 * r10 + i10 * i10) + (r11 * r11 + i11 * i11);

            const float y  = fmaf(q, __ldg(&fc3w[0]), __ldg(&fc3b[0]));
            const float l0 = y, l1 = 1.0f - y;
            const float m  = fmaxf(l0, l1);
            const float lse = m + logf(expf(l0 - m) + expf(l1 - m));

            float2 res;
            res.x = l0 - lse;
            res.y = l1 - lse;
            ((float2*)out)[sb + lane] = res;
        }
        __syncwarp();
    }
}

// ---------------------------------------------------------------------------
extern "C" void kernel_launch(void* const* d_in, const int* in_sizes, int n_in,
                              void* d_out, int out_size) {
    const float* x   = (const float*)d_in[0];
    const float* c1w = (const float*)d_in[1];
    const float* c1b = (const float*)d_in[2];
    const float* c2w = (const float*)d_in[3];
    const float* c2b = (const float*)d_in[4];
    const float* f1w = (const float*)d_in[5];
    const float* f1b = (const float*)d_in[6];
    const float* f2w = (const float*)d_in[7];
    const float* f2b = (const float*)d_in[8];
    const float* f3w = (const float*)d_in[9];
    const float* f3b = (const float*)d_in[10];
    const float* qp  = (const float*)d_in[11];
    float* out = (float*)d_out;

    static int smem_set = 0;
    if (!smem_set) {
        cudaFuncSetAttribute(k_conv, cudaFuncAttributeMaxDynamicSharedMemorySize, CONV_SMEM);
        cudaFuncSetAttribute(k_fc, cudaFuncAttributeMaxDynamicSharedMemorySize, FC_SMEM);
        smem_set = 1;
    }
    k_conv<<<B_TOTAL / 2 / NPAIR, 256, CONV_SMEM>>>(x, c1w, c1b, c2w, c2b);
    k_fc<<<256, 256, FC_SMEM>>>(f1w, f1b, f2w, f2b, f3w, f3b, qp, out);
}

// round 17
// speedup vs baseline: 1.4056x; 1.4056x over previous
#include <cuda_runtime.h>
#include <cuda_bf16.h>
#include <mma.h>
#include <math.h>
#include <stdint.h>

using namespace nvcuda;

#define B_TOTAL 65536
#define NPAIR 16
typedef unsigned long long ull;

// Scratch: conv2 outputs as bf16 hi/lo, [B][256] bf16 = [B][128] u32 each.
__device__ uint32_t g_hi32[B_TOTAL * 128];
__device__ uint32_t g_lo32[B_TOTAL * 128];

// ---- f32x2 helpers -------------------------------------------------------
__device__ __forceinline__ ull pack2(float a, float b) {
    ull r; asm("mov.b64 %0, {%1,%2};" : "=l"(r) : "f"(a), "f"(b)); return r;
}
__device__ __forceinline__ void unpk(ull v, float& a, float& b) {
    asm("mov.b64 {%0,%1}, %2;" : "=f"(a), "=f"(b) : "l"(v));
}
__device__ __forceinline__ void ffma2(ull& d, ull a, ull b) {
    asm("fma.rn.f32x2 %0, %1, %2, %0;" : "+l"(d) : "l"(a), "l"(b));
}
__device__ __forceinline__ ull add2(ull a, ull b) {
    ull r; asm("add.rn.f32x2 %0, %1, %2;" : "=l"(r) : "l"(a), "l"(b)); return r;
}

// ---- bf16 pack helpers: result = bf16(lo16) | bf16(hi16)<<16 ----
__device__ __forceinline__ uint32_t cvt2bf(float lo16, float hi16) {
    uint32_t r;
    asm("cvt.rn.satfinite.bf16x2.f32 %0, %1, %2;" : "=r"(r) : "f"(hi16), "f"(lo16));
    return r;
}
__device__ __forceinline__ float bflo_f(uint32_t r) { return __uint_as_float(r << 16); }
__device__ __forceinline__ float bfhi_f(uint32_t r) { return __uint_as_float(r & 0xffff0000u); }

// sp1 padded layout: [ci][row 0..11][col 0..11], idx = ci*170 + row*14 + col
#define SP1_CI 170
#define SP1_ROW 14
#define SP1_SZ 340

__device__ __forceinline__ void stage_pair(ull* buf, const float* __restrict__ x,
                                           long b0, int tid, int nt) {
    const float4* A = (const float4*)(x + b0 * 784);
    const float4* C = (const float4*)(x + (b0 + 1) * 784);
    for (int i = tid; i < 196; i += nt) {
        float4 a4 = __ldg(&A[i]), c4 = __ldg(&C[i]);
        ulonglong2 v01, v23;
        v01.x = pack2(a4.x, c4.x); v01.y = pack2(a4.y, c4.y);
        v23.x = pack2(a4.z, c4.z); v23.y = pack2(a4.w, c4.w);
        *(ulonglong2*)&buf[4 * i]     = v01;
        *(ulonglong2*)&buf[4 * i + 2] = v23;
    }
}

// ---------------------------------------------------------------------------
// Persistent warp-specialized conv kernel (R13 version — proven, at its
// f32x2 issue floor). ph2 stores bf16 hi/lo pairs at stride 128 u32/sample.
// ---------------------------------------------------------------------------
__global__ void __launch_bounds__(256, 2) k_conv(const float* __restrict__ x,
                                                 const float* __restrict__ w1,
                                                 const float* __restrict__ b1,
                                                 const float* __restrict__ w2,
                                                 const float* __restrict__ b2) {
    __shared__ __align__(16) ull sx[2][784];
    __shared__ __align__(16) ull sp1[2][SP1_SZ];
    const int t = threadIdx.x;
    const long pair0 = (long)blockIdx.x * NPAIR;

    ull wreg[25];
    float bias = 0.f;
    int co1 = 0, py1 = 0, pxh1 = 0;
    int co2 = 0, ci2 = 0, py2 = 0;

    if (t < 96) {
        co1 = t / 48;
        const int rem = t % 48;
        py1 = rem >> 2; pxh1 = rem & 3;
#pragma unroll
        for (int i = 0; i < 25; i++) {
            float w = __ldg(&w1[co1 * 25 + i]);
            wreg[i] = pack2(w, w);
        }
        bias = __ldg(&b1[co1]);
    } else if (t >= 128) {
        const int u = t - 128;
        co2 = u >> 3; ci2 = (u >> 2) & 1; py2 = u & 3;
#pragma unroll
        for (int i = 0; i < 25; i++) {
            float w = __ldg(&w2[(co2 * 2 + ci2) * 25 + i]);
            wreg[i] = pack2(w, w);
        }
        bias = __ldg(&b2[co2]);
    }

    stage_pair(sx[0], x, pair0 * 2, t, 256);
    __syncthreads();

    for (int it = 0; it <= NPAIR; it++) {
        if (t < 96) {
            if (it < NPAIR) {
                const ull* in = &sx[it & 1][(2 * py1) * 28 + 6 * pxh1];
                ull acc[2][6] = {{0,0,0,0,0,0},{0,0,0,0,0,0}};
#pragma unroll
                for (int iy = 0; iy < 6; iy++) {
                    ull row[10];
#pragma unroll
                    for (int c = 0; c < 10; c += 2) {
                        ulonglong2 v = *(const ulonglong2*)&in[iy * 28 + c];
                        row[c] = v.x; row[c + 1] = v.y;
                    }
#pragma unroll
                    for (int yy = 0; yy < 2; yy++) {
                        const int ky = iy - yy;
                        if (ky >= 0 && ky < 5) {
#pragma unroll
                            for (int cx = 0; cx < 6; cx++)
#pragma unroll
                                for (int kx = 0; kx < 5; kx++)
                                    ffma2(acc[yy][cx], row[cx + kx], wreg[ky * 5 + kx]);
                        }
                    }
                }
                ull* op = &sp1[it & 1][co1 * SP1_CI + py1 * SP1_ROW + pxh1 * 3];
#pragma unroll
                for (int q = 0; q < 3; q++) {
                    float a0,a1,e0,e1,c0,c1,d0,d1;
                    unpk(acc[0][2*q],   a0,a1); unpk(acc[0][2*q+1], e0,e1);
                    unpk(acc[1][2*q],   c0,c1); unpk(acc[1][2*q+1], d0,d1);
                    float vA = fmaxf(fmaxf(fmaxf(a0,e0), fmaxf(c0,d0)) + bias, 0.f);
                    float vB = fmaxf(fmaxf(fmaxf(a1,e1), fmaxf(c1,d1)) + bias, 0.f);
                    op[q] = pack2(vA, vB);
                }
            }
        } else if (t < 128) {
            if (it + 1 < NPAIR)
                stage_pair(sx[(it + 1) & 1], x, (pair0 + it + 1) * 2, t - 96, 32);
        } else {
            if (it >= 1) {
                const long b0 = (pair0 + it - 1) * 2;
                const ull* in2 = &sp1[(it - 1) & 1][ci2 * SP1_CI + (2 * py2) * SP1_ROW];
                ull acc[2][8];
#pragma unroll
                for (int yy = 0; yy < 2; yy++)
#pragma unroll
                    for (int xx = 0; xx < 8; xx++) acc[yy][xx] = 0ULL;
#pragma unroll
                for (int iy = 0; iy < 6; iy++) {
                    ull row[12];
#pragma unroll
                    for (int c = 0; c < 12; c += 2) {
                        ulonglong2 v = *(const ulonglong2*)&in2[iy * SP1_ROW + c];
                        row[c] = v.x; row[c + 1] = v.y;
                    }
#pragma unroll
                    for (int yy = 0; yy < 2; yy++) {
                        const int ky = iy - yy;
                        if (ky >= 0 && ky < 5) {
#pragma unroll
                            for (int xx = 0; xx < 8; xx++)
#pragma unroll
                                for (int kx = 0; kx < 5; kx++)
                                    ffma2(acc[yy][xx], row[xx + kx], wreg[ky * 5 + kx]);
                        }
                    }
                }
#pragma unroll
                for (int yy = 0; yy < 2; yy++)
#pragma unroll
                    for (int xx = 0; xx < 8; xx++) {
                        ull o = __shfl_xor_sync(0xffffffffu, acc[yy][xx], 4);
                        acc[yy][xx] = add2(acc[yy][xx], o);
                    }
                if (ci2 == 0) {
                    float pA[4], pB[4];
#pragma unroll
                    for (int q = 0; q < 4; q++) {
                        float a0,a1,e0,e1,c0,c1,d0,d1;
                        unpk(acc[0][2*q],   a0,a1); unpk(acc[0][2*q+1], e0,e1);
                        unpk(acc[1][2*q],   c0,c1); unpk(acc[1][2*q+1], d0,d1);
                        pA[q] = fmaxf(fmaxf(fmaxf(a0,e0), fmaxf(c0,d0)) + bias, 0.f);
                        pB[q] = fmaxf(fmaxf(fmaxf(a1,e1), fmaxf(c1,d1)) + bias, 0.f);
                    }
                    uint32_t hA01 = cvt2bf(pA[0], pA[1]);
                    uint32_t hA23 = cvt2bf(pA[2], pA[3]);
                    uint32_t lA01 = cvt2bf(pA[0] - bflo_f(hA01), pA[1] - bfhi_f(hA01));
                    uint32_t lA23 = cvt2bf(pA[2] - bflo_f(hA23), pA[3] - bfhi_f(hA23));
                    uint32_t hB01 = cvt2bf(pB[0], pB[1]);
                    uint32_t hB23 = cvt2bf(pB[2], pB[3]);
                    uint32_t lB01 = cvt2bf(pB[0] - bflo_f(hB01), pB[1] - bfhi_f(hB01));
                    uint32_t lB23 = cvt2bf(pB[2] - bflo_f(hB23), pB[3] - bfhi_f(hB23));
                    const int off = co2 * 8 + py2 * 2;
                    *(uint2*)&g_hi32[b0 * 128 + off]       = make_uint2(hA01, hA23);
                    *(uint2*)&g_lo32[b0 * 128 + off]       = make_uint2(lA01, lA23);
                    *(uint2*)&g_hi32[(b0 + 1) * 128 + off] = make_uint2(hB01, hB23);
                    *(uint2*)&g_lo32[(b0 + 1) * 128 + off] = make_uint2(lB01, lB23);
                }
            }
        }
        __syncthreads();
    }
}

// ---------------------------------------------------------------------------
// k_fc: fc1 on wmma bf16 (3-term hi/lo). 32-sample x 64-out warp tile —
// each B-fragment load feeds BOTH m-tiles (B loads halved). A staged in 32-k
// chunks, ldm ALD=40 (80B rows: 16B-aligned for uint4 + wmma; banks 0,20,8,
// 28,16,4,24,12 — conflict-free). Single pass: grid 256 x 8 warps x 32.
// ---------------------------------------------------------------------------
#define WLDM 72
#define ALD  40
#define W_BYTES (256 * WLDM * 2)           // 36864 per copy
#define A_WARP_BYTES (2 * 32 * ALD * 2)    // hi+lo 32x40 bf16 = 5120
#define FC_SMEM (2 * W_BYTES + 8 * A_WARP_BYTES)  // 73728 + 40960 = 114688

__global__ void __launch_bounds__(256, 2) k_fc(const float* __restrict__ fc1w,
                                               const float* __restrict__ fc1b,
                                               const float* __restrict__ fc2w,
                                               const float* __restrict__ fc2b,
                                               const float* __restrict__ fc3w,
                                               const float* __restrict__ fc3b,
                                               const float* __restrict__ qp,
                                               float* __restrict__ out) {
    extern __shared__ __align__(16) char smem[];
    __nv_bfloat16* s_whi = (__nv_bfloat16*)smem;
    __nv_bfloat16* s_wlo = (__nv_bfloat16*)(smem + W_BYTES);
    char* s_awarp_base = smem + 2 * W_BYTES;

    const int tid = threadIdx.x, warp = tid >> 5, lane = tid & 31;

    __nv_bfloat16* s_ahi = (__nv_bfloat16*)(s_awarp_base + warp * A_WARP_BYTES);
    __nv_bfloat16* s_alo = s_ahi + 32 * ALD;
    float* dw = (float*)s_ahi;   // D reuse: 16x64 f32 = 4096 <= 5120

    for (int i = tid; i < 16384; i += 256) {
        const int n = i & 63, k = i >> 6;
        float w = __ldg(&fc1w[n * 256 + k]);
        __nv_bfloat16 hb = __float2bfloat16(w);
        s_whi[k * WLDM + n] = hb;
        s_wlo[k * WLDM + n] = __float2bfloat16(w - __bfloat162float(hb));
    }
    __syncthreads();

    const __nv_bfloat16* ghi = (const __nv_bfloat16*)g_hi32;
    const __nv_bfloat16* glo = (const __nv_bfloat16*)g_lo32;

    const long sb = ((long)blockIdx.x * 8 + warp) * 32;   // 32 samples per warp

    wmma::fragment<wmma::matrix_a, 16, 16, 16, __nv_bfloat16, wmma::row_major> ah[2], al[2];
    wmma::fragment<wmma::matrix_b, 16, 16, 16, __nv_bfloat16, wmma::row_major> bh, bl;
    wmma::fragment<wmma::accumulator, 16, 16, 16, float> acc[2][4];
#pragma unroll
    for (int mt = 0; mt < 2; mt++)
#pragma unroll
        for (int nt = 0; nt < 4; nt++) wmma::fill_fragment(acc[mt][nt], 0.0f);

    for (int ck = 0; ck < 8; ck++) {           // 32-k chunks
        __syncwarp();
        // stage 32 rows x 32 bf16 (4 x 16B segs per row), hi+lo
#pragma unroll
        for (int ii = 0; ii < 4; ii++) {
            const int idx = lane + ii * 32;     // 0..127
            const int row = idx >> 2, seg = idx & 3;
            const long goff = (sb + row) * 256 + ck * 32 + seg * 8;
            *(uint4*)&s_ahi[row * ALD + seg * 8] = __ldg((const uint4*)&ghi[goff]);
            *(uint4*)&s_alo[row * ALD + seg * 8] = __ldg((const uint4*)&glo[goff]);
        }
        __syncwarp();
#pragma unroll
        for (int kcc = 0; kcc < 2; kcc++) {     // 2 k-tiles of 16
            const int k0 = ck * 32 + kcc * 16;
#pragma unroll
            for (int mt = 0; mt < 2; mt++) {
                wmma::load_matrix_sync(ah[mt], s_ahi + (mt * 16) * ALD + kcc * 16, ALD);
                wmma::load_matrix_sync(al[mt], s_alo + (mt * 16) * ALD + kcc * 16, ALD);
            }
#pragma unroll
            for (int nt = 0; nt < 4; nt++) {
                wmma::load_matrix_sync(bh, s_whi + k0 * WLDM + nt * 16, WLDM);
                wmma::load_matrix_sync(bl, s_wlo + k0 * WLDM + nt * 16, WLDM);
#pragma unroll
                for (int mt = 0; mt < 2; mt++) {
                    wmma::mma_sync(acc[mt][nt], ah[mt], bh, acc[mt][nt]);
                    wmma::mma_sync(acc[mt][nt], al[mt], bh, acc[mt][nt]);
                    wmma::mma_sync(acc[mt][nt], ah[mt], bl, acc[mt][nt]);
                }
            }
        }
    }

    // epilogue: two 16-sample halves, D reuses A buffer
#pragma unroll
    for (int mt = 0; mt < 2; mt++) {
        __syncwarp();
#pragma unroll
        for (int nt = 0; nt < 4; nt++)
            wmma::store_matrix_sync(dw + nt * 16, acc[mt][nt], 64, wmma::mem_row_major);
        __syncwarp();

        if (lane < 16) {
            const float* hrow = dw + lane * 64;
            float x0 = __ldg(&fc2b[0]), x1 = __ldg(&fc2b[1]);
#pragma unroll 8
            for (int o = 0; o < 64; o++) {
                const int o2 = (o + lane * 4) & 63;
                float v = fmaxf(hrow[o2] + __ldg(&fc1b[o2]), 0.f);
                x0 = fmaf(v, __ldg(&fc2w[o2]), x0);
                x1 = fmaf(v, __ldg(&fc2w[64 + o2]), x1);
            }

            float cq[8], sq[8];
#pragma unroll
            for (int i = 0; i < 8; i++) {
                float p = __ldg(&qp[i]);
                sincosf(p, &sq[i], &cq[i]);
            }
            const float PI = 3.14159265358979323846f;
            const float ang = (PI - x0) * (PI - x1);
            const float P = x0 + x1, M = x0 - x1;
            float sPp, cPp, sPm, cPm, sMp, cMp, sMm, cMm;
            sincosf(P + ang, &sPp, &cPp);
            sincosf(P - ang, &sPm, &cPm);
            sincosf(M + ang, &sMp, &cMp);
            sincosf(M - ang, &sMm, &cMm);
            float r00 =  0.5f * cPp, i00 = -0.5f * sPp;
            float r01 =  0.5f * cMm, i01 = -0.5f * sMm;
            float r10 =  0.5f * cMp, i10 =  0.5f * sMp;
            float r11 =  0.5f * cPm, i11 =  0.5f * sPm;

#define ROT0(ii) { float cc = cq[ii], s = sq[ii], a, bt;                     \
    a = r00; bt = r10; r00 = cc*a - s*bt; r10 = s*a + cc*bt;                 \
    a = i00; bt = i10; i00 = cc*a - s*bt; i10 = s*a + cc*bt;                 \
    a = r01; bt = r11; r01 = cc*a - s*bt; r11 = s*a + cc*bt;                 \
    a = i01; bt = i11; i01 = cc*a - s*bt; i11 = s*a + cc*bt; }
#define ROT1(ii) { float cc = cq[ii], s = sq[ii], a, bt;                     \
    a = r00; bt = r01; r00 = cc*a - s*bt; r01 = s*a + cc*bt;                 \
    a = i00; bt = i01; i00 = cc*a - s*bt; i01 = s*a + cc*bt;                 \
    a = r10; bt = r11; r10 = cc*a - s*bt; r11 = s*a + cc*bt;                 \
    a = i10; bt = i11; i10 = cc*a - s*bt; i11 = s*a + cc*bt; }
#define CN01 { float tt; tt = r10; r10 = r11; r11 = tt; tt = i10; i10 = i11; i11 = tt; }
#define CN10 { float tt; tt = r01; r01 = r11; r11 = tt; tt = i01; i01 = i11; i11 = tt; }

            ROT0(0); ROT1(1); CN01;
            ROT0(2); ROT1(3); CN10;
            ROT0(4); ROT1(5); CN01;
            ROT0(6); ROT1(7);

#undef ROT0
#undef ROT1
#undef CN01
#undef CN10

            const float q = (r00 * r00 + i00 * i00) - (r01 * r01 + i01 * i01)
                          - (r10 * r10 + i10 * i10) + (r11 * r11 + i11 * i11);

            const float y  = fmaf(q, __ldg(&fc3w[0]), __ldg(&fc3b[0]));
            const float l0 = y, l1 = 1.0f - y;
            const float m  = fmaxf(l0, l1);
            const float lse = m + logf(expf(l0 - m) + expf(l1 - m));

            float2 res;
            res.x = l0 - lse;
            res.y = l1 - lse;
            ((float2*)out)[sb + mt * 16 + lane] = res;
        }
        __syncwarp();
    }
}

// ---------------------------------------------------------------------------
extern "C" void kernel_launch(void* const* d_in, const int* in_sizes, int n_in,
                              void* d_out, int out_size) {
    const float* x   = (const float*)d_in[0];
    const float* c1w = (const float*)d_in[1];
    const float* c1b = (const float*)d_in[2];
    const float* c2w = (const float*)d_in[3];
    const float* c2b = (const float*)d_in[4];
    const float* f1w = (const float*)d_in[5];
    const float* f1b = (const float*)d_in[6];
    const float* f2w = (const float*)d_in[7];
    const float* f2b = (const float*)d_in[8];
    const float* f3w = (const float*)d_in[9];
    const float* f3b = (const float*)d_in[10];
    const float* qp  = (const float*)d_in[11];
    float* out = (float*)d_out;

    static int smem_set = 0;
    if (!smem_set) {
        cudaFuncSetAttribute(k_fc, cudaFuncAttributeMaxDynamicSharedMemorySize, FC_SMEM);
        smem_set = 1;
    }
    k_conv<<<B_TOTAL / 2 / NPAIR, 256>>>(x, c1w, c1b, c2w, c2b);
    k_fc<<<256, 256, FC_SMEM>>>(f1w, f1b, f2w, f2b, f3w, f3b, qp, out);
}